// round 2
// baseline (speedup 1.0000x reference)
#include <cuda_runtime.h>
#include <math.h>

#define NBATCH 2
#define NSEQ   128
#define DIMM   128
#define NHEADS 8
#define DHEAD  64
#define NINNER 512
#define NEDGE  160
#define NROWS  256   // NBATCH*NSEQ
#define NDEPTH 6

// ---------------- device scratch (no allocations allowed) -------------------
__device__ float g_nodes[NROWS * DIMM];
__device__ float g_q    [NROWS * NINNER];
__device__ float g_kT   [NBATCH * NINNER * NSEQ];   // [b][c][j]
__device__ float g_v    [NROWS * NINNER];           // vhat row-major
__device__ float g_att  [NROWS * NINNER];
__device__ float g_ff1  [NROWS * NINNER];
__device__ float g_edges[NBATCH * NSEQ * NSEQ * 3];

__device__ __forceinline__ float warpsum(float v) {
#pragma unroll
    for (int s = 16; s > 0; s >>= 1) v += __shfl_xor_sync(0xffffffffu, v, s);
    return v;
}
__device__ __forceinline__ float warpmax(float v) {
#pragma unroll
    for (int s = 16; s > 0; s >>= 1) v = fmaxf(v, __shfl_xor_sync(0xffffffffu, v, s));
    return v;
}

// ---------------- setup -----------------------------------------------------
__global__ void k_init(const int* __restrict__ indices,
                       const float* __restrict__ atom_emb,
                       const float* __restrict__ noise) {
    int row = blockIdx.x, c = threadIdx.x;
    int idx = indices[row];
    g_nodes[row * DIMM + c] = (c < 127) ? atom_emb[idx * 127 + c] : noise[0];
}

// zero + sequential scatter (last-wins per set, matching jax .at[].set order)
__global__ void k_edges(const float* __restrict__ coords,
                        const int* __restrict__ bonds) {
    int t = threadIdx.x;
    for (int x = t; x < NBATCH * NSEQ * NSEQ * 3; x += 1024) g_edges[x] = 0.f;
    __syncthreads();
    if (t < 6) {
        int b = t / 3, c = t % 3;
        const float* cb = coords + b * NSEQ * 3;
        for (int e = 0; e < NEDGE; e++) {
            int i = bonds[e * 2], j = bonds[e * 2 + 1];
            float d = cb[i * 3 + c] - cb[j * 3 + c];
            g_edges[((b * NSEQ + i) * NSEQ + j) * 3 + c] = d;
        }
        for (int e = 0; e < NEDGE; e++) {
            int i = bonds[e * 2], j = bonds[e * 2 + 1];
            float d = cb[i * 3 + c] - cb[j * 3 + c];
            g_edges[((b * NSEQ + j) * NSEQ + i) * 3 + c] = -d;
        }
    }
}

// ---------------- LN1 + QKV projection (K transposed, be folded) ------------
// grid 64 blocks x 256 threads, 4 rows per block, 6 output cols per thread
__global__ void k_ln1_qkv(const float* __restrict__ lng, const float* __restrict__ lnb,
                          const float* __restrict__ Wq,  const float* __restrict__ bq,
                          const float* __restrict__ Wkv, const float* __restrict__ bkv,
                          const float* __restrict__ be) {
    __shared__ float xn[4][DIMM];
    int tid = threadIdx.x, warp = tid >> 5, lane = tid & 31;
    int r0 = blockIdx.x * 4;
    if (warp < 4) {
        const float* x = g_nodes + (r0 + warp) * DIMM;
        float v0 = x[lane], v1 = x[lane + 32], v2 = x[lane + 64], v3 = x[lane + 96];
        float mean = warpsum(v0 + v1 + v2 + v3) * (1.f / 128.f);
        float d0 = v0 - mean, d1 = v1 - mean, d2 = v2 - mean, d3 = v3 - mean;
        float var = warpsum(d0 * d0 + d1 * d1 + d2 * d2 + d3 * d3) * (1.f / 128.f);
        float inv = rsqrtf(var + 1e-5f);
        xn[warp][lane]      = d0 * inv * lng[lane]      + lnb[lane];
        xn[warp][lane + 32] = d1 * inv * lng[lane + 32] + lnb[lane + 32];
        xn[warp][lane + 64] = d2 * inv * lng[lane + 64] + lnb[lane + 64];
        xn[warp][lane + 96] = d3 * inv * lng[lane + 96] + lnb[lane + 96];
    }
    __syncthreads();

    // col groups: g0,g1 -> q cols tid,tid+256 ; g2,g3 -> khat kv-cols tid,tid+256 ;
    //             g4,g5 -> vhat kv-cols tid+512,tid+768
    const float* wptr[6];
    wptr[0] = Wq  + tid;        wptr[1] = Wq  + tid + 256;
    wptr[2] = Wkv + tid;        wptr[3] = Wkv + tid + 256;
    wptr[4] = Wkv + tid + 512;  wptr[5] = Wkv + tid + 768;

    float acc[6][4];
#pragma unroll
    for (int g = 0; g < 6; g++)
#pragma unroll
        for (int m = 0; m < 4; m++) acc[g][m] = 0.f;

    for (int k = 0; k < DIMM; k++) {
        float x0 = xn[0][k], x1 = xn[1][k], x2 = xn[2][k], x3 = xn[3][k];
#pragma unroll
        for (int g = 0; g < 6; g++) {
            float w = (g < 2) ? wptr[g][k * NINNER] : wptr[g][k * (2 * NINNER)];
            acc[g][0] += w * x0; acc[g][1] += w * x1;
            acc[g][2] += w * x2; acc[g][3] += w * x3;
        }
    }

    float bias[6];
    bias[0] = bq[tid];                       bias[1] = bq[tid + 256];
    bias[2] = bkv[tid]       + be[tid];      bias[3] = bkv[tid + 256] + be[tid + 256];
    bias[4] = bkv[tid + 512] + be[tid];      bias[5] = bkv[tid + 768] + be[tid + 256];

#pragma unroll
    for (int m = 0; m < 4; m++) {
        int row = r0 + m, b = row >> 7, j = row & 127;
        g_q[row * NINNER + tid]       = acc[0][m] + bias[0];
        g_q[row * NINNER + tid + 256] = acc[1][m] + bias[1];
        g_kT[b * NINNER * NSEQ + tid * NSEQ + j]         = acc[2][m] + bias[2];
        g_kT[b * NINNER * NSEQ + (tid + 256) * NSEQ + j] = acc[3][m] + bias[3];
        g_v[row * NINNER + tid]       = acc[4][m] + bias[4];
        g_v[row * NINNER + tid + 256] = acc[5][m] + bias[5];
    }
}

// ---------------- attention: per (b, head, 16-i tile) -----------------------
// grid 128 blocks (b*64 + h*8 + itile) x 256 threads (warp w -> i = it*16+{w, 8+w})
__global__ void k_attn(const float* __restrict__ We) {
    __shared__ float tile[DHEAD * NSEQ];     // khat [d][j], then vhat [j][d]
    __shared__ float attn_s[16][NSEQ];
    int tid = threadIdx.x, w = tid >> 5, lane = tid & 31;
    int blk = blockIdx.x;
    int b = blk >> 6, h = (blk >> 3) & 7, it = blk & 7;

    // phase A: khat tile (contiguous copy: g_kT slice for this (b,h))
    const float* ksrc = g_kT + b * NINNER * NSEQ + h * DHEAD * NSEQ;
    for (int t = tid; t < DHEAD * NSEQ; t += 256) tile[t] = ksrc[t];
    __syncthreads();

    const float* Weh = We + h * DHEAD;
    float ec[2][3];

    for (int ii = 0; ii < 2; ii++) {
        int iloc = ii * 8 + w;
        int i = it * 16 + iloc;
        const float* qp = g_q + (b * NSEQ + i) * NINNER + h * DHEAD;
        float q0 = qp[lane], q1 = qp[lane + 32];
        float qe0 = warpsum(q0 * Weh[lane]              + q1 * Weh[lane + 32]);
        float qe1 = warpsum(q0 * Weh[NINNER + lane]     + q1 * Weh[NINNER + lane + 32]);
        float qe2 = warpsum(q0 * Weh[2 * NINNER + lane] + q1 * Weh[2 * NINNER + lane + 32]);

        float acc0 = 0.f, acc1 = 0.f, acc2 = 0.f, acc3 = 0.f;
        for (int d = 0; d < DHEAD; d++) {
            float qv = __shfl_sync(0xffffffffu, (d < 32) ? q0 : q1, d & 31);
            const float* tr = tile + d * NSEQ + lane;
            acc0 += qv * tr[0];  acc1 += qv * tr[32];
            acc2 += qv * tr[64]; acc3 += qv * tr[96];
        }
        const float* eb = g_edges + (b * NSEQ + i) * NSEQ * 3;
        float s[4], E[4][3];
        float accs[4] = {acc0, acc1, acc2, acc3};
#pragma unroll
        for (int jj = 0; jj < 4; jj++) {
            int j = lane + jj * 32;
            E[jj][0] = eb[j * 3];
            E[jj][1] = eb[j * 3 + 1];
            E[jj][2] = eb[j * 3 + 2];
            s[jj] = (accs[jj] + qe0 * E[jj][0] + qe1 * E[jj][1] + qe2 * E[jj][2]) * 0.125f;
        }
        float mx = warpmax(fmaxf(fmaxf(s[0], s[1]), fmaxf(s[2], s[3])));
        float p[4], sum = 0.f;
#pragma unroll
        for (int jj = 0; jj < 4; jj++) { p[jj] = expf(s[jj] - mx); sum += p[jj]; }
        sum = warpsum(sum);
        float inv = 1.f / sum;
        float e0 = 0.f, e1 = 0.f, e2 = 0.f;
#pragma unroll
        for (int jj = 0; jj < 4; jj++) {
            float a = p[jj] * inv;
            attn_s[iloc][lane + jj * 32] = a;
            e0 += a * E[jj][0]; e1 += a * E[jj][1]; e2 += a * E[jj][2];
        }
        ec[ii][0] = warpsum(e0); ec[ii][1] = warpsum(e1); ec[ii][2] = warpsum(e2);
    }
    __syncthreads();

    // phase B: vhat tile [j][d] (reuse smem)
    const float* vsrc = g_v + b * NSEQ * NINNER + h * DHEAD;
    for (int t = tid; t < DHEAD * NSEQ; t += 256) {
        int j = t >> 6, d = t & 63;
        tile[j * DHEAD + d] = vsrc[j * NINNER + d];
    }
    __syncthreads();

    for (int ii = 0; ii < 2; ii++) {
        int iloc = ii * 8 + w;
        int i = it * 16 + iloc;
        float o0 = 0.f, o1 = 0.f;
        int d0 = lane, d1 = lane + 32;
        for (int j = 0; j < NSEQ; j++) {
            float a = attn_s[iloc][j];
            o0 += a * tile[j * DHEAD + d0];
            o1 += a * tile[j * DHEAD + d1];
        }
        o0 += ec[ii][0] * Weh[d0] + ec[ii][1] * Weh[NINNER + d0] + ec[ii][2] * Weh[2 * NINNER + d0];
        o1 += ec[ii][0] * Weh[d1] + ec[ii][1] * Weh[NINNER + d1] + ec[ii][2] * Weh[2 * NINNER + d1];
        float* op = g_att + (b * NSEQ + i) * NINNER + h * DHEAD;
        op[d0] = o0; op[d1] = o1;
    }
}

// ---------------- proj (512->128) + gated residual, writes g_nodes ----------
// useFF=0: X=g_att (Wo path), useFF=1: X=g_ff1 (W2 path). grid 256 x 128.
__global__ void k_proj_gate(int useFF, const float* __restrict__ W,
                            const float* __restrict__ bv, const float* __restrict__ Wg) {
    __shared__ float xs[NINNER];
    __shared__ float red[4];
    __shared__ float gsh;
    int row = blockIdx.x, tid = threadIdx.x, warp = tid >> 5, lane = tid & 31;
    const float* X = useFF ? g_ff1 : g_att;
#pragma unroll
    for (int q = 0; q < 4; q++) xs[tid + q * 128] = X[row * NINNER + tid + q * 128];
    __syncthreads();
    float a0 = 0.f, a1 = 0.f, a2 = 0.f, a3 = 0.f;
    for (int k = 0; k < NINNER; k += 4) {
        a0 += xs[k]     * W[k * DIMM + tid];
        a1 += xs[k + 1] * W[(k + 1) * DIMM + tid];
        a2 += xs[k + 2] * W[(k + 2) * DIMM + tid];
        a3 += xs[k + 3] * W[(k + 3) * DIMM + tid];
    }
    float x = a0 + a1 + a2 + a3 + bv[tid];
    float res = g_nodes[row * DIMM + tid];
    float t = x * Wg[tid] + res * Wg[DIMM + tid] + (x - res) * Wg[2 * DIMM + tid];
    t = warpsum(t);
    if (lane == 0) red[warp] = t;
    __syncthreads();
    if (tid == 0) {
        float s = red[0] + red[1] + red[2] + red[3];
        gsh = 1.f / (1.f + expf(-s));
    }
    __syncthreads();
    float g = gsh;
    g_nodes[row * DIMM + tid] = x * g + res * (1.f - g);
}

// ---------------- LN2 + FF1 (128->512) + exact GELU -------------------------
__global__ void k_ln2_ff1(const float* __restrict__ lng, const float* __restrict__ lnb,
                          const float* __restrict__ W1,  const float* __restrict__ b1) {
    __shared__ float xn[DIMM];
    __shared__ float red[4];
    int row = blockIdx.x, tid = threadIdx.x, warp = tid >> 5, lane = tid & 31;
    float x = g_nodes[row * DIMM + tid];
    float t = warpsum(x);
    if (lane == 0) red[warp] = t;
    __syncthreads();
    float mean = (red[0] + red[1] + red[2] + red[3]) * (1.f / 128.f);
    float d = x - mean;
    __syncthreads();
    t = warpsum(d * d);
    if (lane == 0) red[warp] = t;
    __syncthreads();
    float var = (red[0] + red[1] + red[2] + red[3]) * (1.f / 128.f);
    float inv = rsqrtf(var + 1e-5f);
    xn[tid] = d * inv * lng[tid] + lnb[tid];
    __syncthreads();
    float a[4] = {0.f, 0.f, 0.f, 0.f};
    for (int k = 0; k < DIMM; k++) {
        float xv = xn[k];
#pragma unroll
        for (int q = 0; q < 4; q++) a[q] += xv * W1[k * NINNER + tid + q * 128];
    }
#pragma unroll
    for (int q = 0; q < 4; q++) {
        float z = a[q] + b1[tid + q * 128];
        float y = 0.5f * z * (1.f + erff(z * 0.70710678118654752f));
        g_ff1[row * NINNER + tid + q * 128] = y;
    }
}

// ---------------- final scalar reduction ------------------------------------
__global__ void k_final(const float* __restrict__ Wlin, const float* __restrict__ blin,
                        float* __restrict__ out) {
    __shared__ float red[8];
    int tid = threadIdx.x, warp = tid >> 5, lane = tid & 31;
    float s = 0.f;
    const float* xr = g_nodes + tid * DIMM;
    for (int c = 0; c < DIMM; c++) s += xr[c] * Wlin[c];
    s = warpsum(s);
    if (lane == 0) red[warp] = s;
    __syncthreads();
    if (tid == 0) {
        float t = 0.f;
        for (int q = 0; q < 8; q++) t += red[q];
        out[0] = t + 256.f * blin[0];
    }
}

// ---------------- launch -----------------------------------------------------
extern "C" void kernel_launch(void* const* d_in, const int* in_sizes, int n_in,
                              void* d_out, int out_size) {
    const int*   indices  = (const int*)  d_in[0];
    const float* coords   = (const float*)d_in[1];
    const int*   bonds    = (const int*)  d_in[2];
    const float* noise    = (const float*)d_in[3];
    const float* atom_emb = (const float*)d_in[4];
    const float* ln1g     = (const float*)d_in[5];
    const float* ln1b     = (const float*)d_in[6];
    const float* Wq       = (const float*)d_in[7];
    const float* bq       = (const float*)d_in[8];
    const float* Wkv      = (const float*)d_in[9];
    const float* bkv      = (const float*)d_in[10];
    const float* We       = (const float*)d_in[11];
    const float* be       = (const float*)d_in[12];
    const float* Wo       = (const float*)d_in[13];
    const float* bo       = (const float*)d_in[14];
    const float* Wg1      = (const float*)d_in[15];
    const float* ln2g     = (const float*)d_in[16];
    const float* ln2b     = (const float*)d_in[17];
    const float* W1       = (const float*)d_in[18];
    const float* b1       = (const float*)d_in[19];
    const float* W2       = (const float*)d_in[20];
    const float* b2       = (const float*)d_in[21];
    const float* Wg2      = (const float*)d_in[22];
    const float* Wlin     = (const float*)d_in[23];
    const float* blin     = (const float*)d_in[24];

    k_init<<<NROWS, DIMM>>>(indices, atom_emb, noise);
    k_edges<<<1, 1024>>>(coords, bonds);

    for (int l = 0; l < NDEPTH; l++) {
        k_ln1_qkv<<<64, 256>>>(ln1g + l * DIMM, ln1b + l * DIMM,
                               Wq + l * DIMM * NINNER, bq + l * NINNER,
                               Wkv + l * DIMM * 2 * NINNER, bkv + l * 2 * NINNER,
                               be + l * NINNER);
        k_attn<<<128, 256>>>(We + l * 3 * NINNER);
        k_proj_gate<<<NROWS, DIMM>>>(0, Wo + l * NINNER * DIMM, bo + l * DIMM,
                                     Wg1 + l * 3 * DIMM);
        k_ln2_ff1<<<NROWS, DIMM>>>(ln2g + l * DIMM, ln2b + l * DIMM,
                                   W1 + l * DIMM * NINNER, b1 + l * NINNER);
        k_proj_gate<<<NROWS, DIMM>>>(1, W2 + l * NINNER * DIMM, b2 + l * DIMM,
                                     Wg2 + l * 3 * DIMM);
    }
    k_final<<<1, 256>>>(Wlin, blin, (float*)d_out);
}

// round 3
// speedup vs baseline: 1.6291x; 1.6291x over previous
#include <cuda_runtime.h>
#include <math.h>

#define G      128
#define T      256
#define NB     2
#define NN     128
#define DM     128
#define NH     8
#define DH     64
#define NI     512
#define NEDGE  160

// ---------------- device scratch ------------------------------------------
__device__ float g_nodes[256 * 128];
__device__ float g_xn   [256 * 128];
__device__ float g_q    [256 * 512];
__device__ float g_kT   [2 * 512 * 128];   // [b][c][j]
__device__ float g_v    [256 * 512];       // row-major
__device__ float g_att  [256 * 512];
__device__ float g_edges[2 * 128 * 128 * 3];
__device__ float g_part [G];

__device__ unsigned int          g_cnt[8];
__device__ unsigned int          g_root;
__device__ volatile unsigned int g_epoch;

__device__ __forceinline__ float warpsum(float v) {
#pragma unroll
    for (int s = 16; s > 0; s >>= 1) v += __shfl_xor_sync(0xffffffffu, v, s);
    return v;
}
__device__ __forceinline__ float warpmax(float v) {
#pragma unroll
    for (int s = 16; s > 0; s >>= 1) v = fmaxf(v, __shfl_xor_sync(0xffffffffu, v, s));
    return v;
}

// two-level grid barrier (128 blocks = 8 groups x 16)
__device__ __forceinline__ void gbar(int bid) {
    __syncthreads();
    if (threadIdx.x == 0) {
        __threadfence();
        unsigned int e = g_epoch;
        unsigned int t = atomicAdd(&g_cnt[bid & 7], 1u);
        if (t == 15u) {
            g_cnt[bid & 7] = 0u;
            unsigned int r = atomicAdd(&g_root, 1u);
            if (r == 7u) {
                g_root = 0u;
                __threadfence();
                g_epoch = e + 1u;
            } else {
                while (g_epoch == e) {}
            }
        } else {
            while (g_epoch == e) {}
        }
        __threadfence();
    }
    __syncthreads();
}

// per-half-block (128-thread) sum; all 256 threads must call
__device__ __forceinline__ float halfsum(float v, int tid, float* red) {
    v = warpsum(v);
    int w = tid >> 5;
    if ((tid & 31) == 0) red[w] = v;
    __syncthreads();
    int base = w & 4;
    float s = red[base] + red[base + 1] + red[base + 2] + red[base + 3];
    __syncthreads();
    return s;
}

__global__ void __launch_bounds__(T, 1)
fused_kernel(const int* __restrict__ indices, const float* __restrict__ coords,
             const int* __restrict__ bonds,   const float* __restrict__ noise,
             const float* __restrict__ atom_emb,
             const float* __restrict__ ln1g, const float* __restrict__ ln1b,
             const float* __restrict__ Wq,   const float* __restrict__ bq,
             const float* __restrict__ Wkv,  const float* __restrict__ bkv,
             const float* __restrict__ We,   const float* __restrict__ be,
             const float* __restrict__ Wo,   const float* __restrict__ bo,
             const float* __restrict__ Wg1,
             const float* __restrict__ ln2g, const float* __restrict__ ln2b,
             const float* __restrict__ W1,   const float* __restrict__ b1,
             const float* __restrict__ W2,   const float* __restrict__ b2,
             const float* __restrict__ Wg2,
             const float* __restrict__ Wlin, const float* __restrict__ blin,
             float* __restrict__ out) {
    __shared__ float sm[11776];   // 46 KB
    int bid = blockIdx.x, tid = threadIdx.x;
    int lane = tid & 31, warp = tid >> 5;

    // ================= SETUP ==============================================
    {
        int basez = bid * 768;
        g_edges[basez + tid] = 0.f;
        g_edges[basez + tid + 256] = 0.f;
        g_edges[basez + tid + 512] = 0.f;

        int rl = tid >> 7, c = tid & 127;
        int row = 2 * bid + rl;
        float val = (c < 127) ? atom_emb[indices[row] * 127 + c] : noise[0];
        g_nodes[row * 128 + c] = val;
        float mean = halfsum(val, tid, sm) * (1.f / 128.f);
        float d = val - mean;
        float var = halfsum(d * d, tid, sm) * (1.f / 128.f);
        g_xn[row * 128 + c] = d * rsqrtf(var + 1e-5f) * ln1g[c] + ln1b[c];
    }
    gbar(bid);

    // ================= LAYER LOOP =========================================
    for (int l = 0; l < 6; l++) {
        // ---------- QKV GEMM (96 tiles: 8 row-tiles x 12 col-tiles) -------
        if (bid < 96) {
            const float* Wq_l  = Wq  + l * 128 * 512;
            const float* Wkv_l = Wkv + l * 128 * 1024;
            int rt = bid / 12, ct = bid % 12;
            int r0 = rt * 32;
            float* xs = sm;                             // 32x128
            {
                const float4* src = (const float4*)(g_xn + r0 * 128);
                float4* dst = (float4*)xs;
#pragma unroll
                for (int t = 0; t < 4; t++) dst[tid + t * 256] = src[tid + t * 256];
            }
            __syncthreads();
            int tx = tid & 31, ty = tid >> 5;
            int cglob = ct * 128 + tx * 4;
            const float* W; int ld, cs;
            float4 bias;
            if (cglob < 512) {
                W = Wq_l; ld = 512; cs = cglob;
                bias = *(const float4*)&bq[l * 512 + cglob];
            } else {
                W = Wkv_l; ld = 1024; cs = cglob - 512;
                int cc = (cglob < 1024) ? (cglob - 512) : (cglob - 1024);
                float4 bb = *(const float4*)&bkv[l * 1024 + cs];
                float4 bee = *(const float4*)&be[l * 512 + cc];
                bias.x = bb.x + bee.x; bias.y = bb.y + bee.y;
                bias.z = bb.z + bee.z; bias.w = bb.w + bee.w;
            }
            float acc[4][4];
#pragma unroll
            for (int r = 0; r < 4; r++) { acc[r][0]=0.f; acc[r][1]=0.f; acc[r][2]=0.f; acc[r][3]=0.f; }
#pragma unroll 4
            for (int k = 0; k < 128; k++) {
                float4 w4 = *(const float4*)&W[k * ld + cs];
#pragma unroll
                for (int r = 0; r < 4; r++) {
                    float x = xs[(ty * 4 + r) * 128 + k];
                    acc[r][0] += x * w4.x; acc[r][1] += x * w4.y;
                    acc[r][2] += x * w4.z; acc[r][3] += x * w4.w;
                }
            }
#pragma unroll
            for (int r = 0; r < 4; r++) {
                int row = r0 + ty * 4 + r;
                float4 o;
                o.x = acc[r][0] + bias.x; o.y = acc[r][1] + bias.y;
                o.z = acc[r][2] + bias.z; o.w = acc[r][3] + bias.w;
                if (cglob < 512) {
                    *(float4*)&g_q[row * 512 + cglob] = o;
                } else if (cglob < 1024) {
                    int b = row >> 7, j = row & 127, kc = cglob - 512;
                    g_kT[(b * 512 + kc    ) * 128 + j] = o.x;
                    g_kT[(b * 512 + kc + 1) * 128 + j] = o.y;
                    g_kT[(b * 512 + kc + 2) * 128 + j] = o.z;
                    g_kT[(b * 512 + kc + 3) * 128 + j] = o.w;
                } else {
                    *(float4*)&g_v[row * 512 + (cglob - 1024)] = o;
                }
            }
        } else if (bid == 96 && l == 0) {
            // ---------- edge scatter (runs concurrently with QKV L0) ------
            int* bnd = (int*)sm;            // 320 ints
            int* win = (int*)(sm + 512);    // 160 ints
            for (int t = tid; t < 320; t += 256) bnd[t] = bonds[t];
            __syncthreads();
            if (tid < 160) {
                int i = bnd[tid * 2], j = bnd[tid * 2 + 1], w = 1;
                for (int e = tid + 1; e < 160; e++)
                    if (bnd[e * 2] == i && bnd[e * 2 + 1] == j) { w = 0; break; }
                win[tid] = w;
            }
            __syncthreads();
            if (tid < 160 && win[tid]) {
                int i = bnd[tid * 2], j = bnd[tid * 2 + 1];
                for (int b = 0; b < 2; b++) {
                    const float* cb = coords + b * 384;
                    float dx = cb[i*3]-cb[j*3], dy = cb[i*3+1]-cb[j*3+1], dz = cb[i*3+2]-cb[j*3+2];
                    float* p = &g_edges[((b * 128 + i) * 128 + j) * 3];
                    p[0] = dx; p[1] = dy; p[2] = dz;
                }
            }
            __syncthreads();
            if (tid < 160 && win[tid]) {
                int i = bnd[tid * 2], j = bnd[tid * 2 + 1];
                for (int b = 0; b < 2; b++) {
                    const float* cb = coords + b * 384;
                    float dx = cb[i*3]-cb[j*3], dy = cb[i*3+1]-cb[j*3+1], dz = cb[i*3+2]-cb[j*3+2];
                    float* p = &g_edges[((b * 128 + j) * 128 + i) * 3];
                    p[0] = -dx; p[1] = -dy; p[2] = -dz;
                }
            }
        }
        gbar(bid);

        // ---------- ATTENTION (128 jobs: b x h x itile) -------------------
        {
            const float* We_l = We + l * 3 * 512;
            int b = bid >> 6, h = (bid >> 3) & 7, it = bid & 7;
            float* tile = sm;           // 8192 f
            float* qs   = sm + 8192;    // 1024 f
            float* aps  = sm + 9216;    // 2048 f
            float* wsh  = sm + 11264;   // 192 f
            {
                const float4* ks = (const float4*)(g_kT + (b * 512 + h * 64) * 128);
                float4* td = (float4*)tile;
#pragma unroll
                for (int t = 0; t < 8; t++) td[tid + t * 256] = ks[tid + t * 256];
            }
            {
                const float* qb = g_q + (b * 128 + it * 16) * 512 + h * 64;
                int i16 = tid >> 4, dq = (tid & 15) * 4;
                *(float4*)&qs[i16 * 64 + dq] = *(const float4*)&qb[i16 * 512 + dq];
            }
            if (tid < 192) {
                int c = tid / 64, d = tid % 64;
                wsh[tid] = We_l[c * 512 + h * 64 + d];
            }
            __syncthreads();

            float ecr[2][3];
#pragma unroll
            for (int ii = 0; ii < 2; ii++) {
                int il = ii * 8 + warp;
                int i  = it * 16 + il;
                float q0 = qs[il * 64 + lane], q1 = qs[il * 64 + 32 + lane];
                float qe0 = warpsum(q0 * wsh[lane]       + q1 * wsh[32 + lane]);
                float qe1 = warpsum(q0 * wsh[64 + lane]  + q1 * wsh[96 + lane]);
                float qe2 = warpsum(q0 * wsh[128 + lane] + q1 * wsh[160 + lane]);

                float ax = 0.f, ay = 0.f, az = 0.f, aw = 0.f;
#pragma unroll 16
                for (int d = 0; d < 64; d++) {
                    float qv = qs[il * 64 + d];
                    float4 kt = *(float4*)&tile[d * 128 + lane * 4];
                    ax += qv * kt.x; ay += qv * kt.y; az += qv * kt.z; aw += qv * kt.w;
                }
                const float* eb = g_edges + (b * 128 + i) * 384 + lane * 12;
                float4 ea  = *(const float4*)(eb);
                float4 eb4 = *(const float4*)(eb + 4);
                float4 ec4 = *(const float4*)(eb + 8);
                float E0x=ea.x, E0y=ea.y, E0z=ea.z;
                float E1x=ea.w, E1y=eb4.x, E1z=eb4.y;
                float E2x=eb4.z, E2y=eb4.w, E2z=ec4.x;
                float E3x=ec4.y, E3y=ec4.z, E3z=ec4.w;
                float s0 = (ax + qe0*E0x + qe1*E0y + qe2*E0z) * 0.125f;
                float s1 = (ay + qe0*E1x + qe1*E1y + qe2*E1z) * 0.125f;
                float s2 = (az + qe0*E2x + qe1*E2y + qe2*E2z) * 0.125f;
                float s3 = (aw + qe0*E3x + qe1*E3y + qe2*E3z) * 0.125f;
                float mx = warpmax(fmaxf(fmaxf(s0, s1), fmaxf(s2, s3)));
                float p0 = expf(s0 - mx), p1 = expf(s1 - mx), p2 = expf(s2 - mx), p3 = expf(s3 - mx);
                float sum = warpsum(p0 + p1 + p2 + p3);
                float inv = 1.f / sum;
                p0 *= inv; p1 *= inv; p2 *= inv; p3 *= inv;
                *(float4*)&aps[il * 128 + lane * 4] = make_float4(p0, p1, p2, p3);
                ecr[ii][0] = warpsum(p0*E0x + p1*E1x + p2*E2x + p3*E3x);
                ecr[ii][1] = warpsum(p0*E0y + p1*E1y + p2*E2y + p3*E3y);
                ecr[ii][2] = warpsum(p0*E0z + p1*E1z + p2*E2z + p3*E3z);
            }
            __syncthreads();
            {   // v tile [j][64]
                const float* vb = g_v + (b * 128) * 512 + h * 64;
#pragma unroll
                for (int t = 0; t < 8; t++) {
                    int idx = tid + t * 256;
                    int j = idx >> 4, dq = (idx & 15) * 4;
                    *(float4*)&tile[j * 64 + dq] = *(const float4*)&vb[j * 512 + dq];
                }
            }
            __syncthreads();
#pragma unroll
            for (int ii = 0; ii < 2; ii++) {
                int il = ii * 8 + warp;
                int i  = it * 16 + il;
                int d0 = lane * 2;
                float ox = 0.f, oy = 0.f;
#pragma unroll 4
                for (int jc = 0; jc < 32; jc++) {
                    float4 a4 = *(float4*)&aps[il * 128 + jc * 4];
                    float2 v0 = *(float2*)&tile[(jc * 4 + 0) * 64 + d0];
                    float2 v1 = *(float2*)&tile[(jc * 4 + 1) * 64 + d0];
                    float2 v2 = *(float2*)&tile[(jc * 4 + 2) * 64 + d0];
                    float2 v3 = *(float2*)&tile[(jc * 4 + 3) * 64 + d0];
                    ox += a4.x * v0.x + a4.y * v1.x + a4.z * v2.x + a4.w * v3.x;
                    oy += a4.x * v0.y + a4.y * v1.y + a4.z * v2.y + a4.w * v3.y;
                }
                ox += ecr[ii][0]*wsh[d0]   + ecr[ii][1]*wsh[64+d0]   + ecr[ii][2]*wsh[128+d0];
                oy += ecr[ii][0]*wsh[d0+1] + ecr[ii][1]*wsh[64+d0+1] + ecr[ii][2]*wsh[128+d0+1];
                *(float2*)&g_att[(b * 128 + i) * 512 + h * 64 + d0] = make_float2(ox, oy);
            }
        }
        gbar(bid);

        // ---------- POST: Wo+gate+LN2+FF1+GELU+FF2+gate+LN1(next) ---------
        {
            const float* Wo_l  = Wo  + l * 512 * 128;
            const float* W1_l  = W1  + l * 128 * 512;
            const float* W2_l  = W2  + l * 512 * 128;
            float* xs  = sm;            // 1024
            float* ps  = sm + 1024;     // 1024
            float* xn2 = sm + 2048;     // 256
            float* nod = sm + 2304;     // 256
            float* ffs = sm + 2560;     // 1024
            float* red = sm + 3584;     // 16
            int r0 = 2 * bid;
            ((float4*)xs)[tid] = ((const float4*)(g_att + r0 * 512))[tid];
            __syncthreads();
            int tx = tid & 31, ty = tid >> 5;
            int rowl = ty & 1, ksl = ty >> 1;
            {   // Wo proj, K split 4 ways
                float4 acc = make_float4(0.f, 0.f, 0.f, 0.f);
                int kb = ksl * 128;
#pragma unroll 4
                for (int k = 0; k < 128; k++) {
                    float a = xs[rowl * 512 + kb + k];
                    float4 w = *(const float4*)&Wo_l[(kb + k) * 128 + tx * 4];
                    acc.x += a * w.x; acc.y += a * w.y; acc.z += a * w.z; acc.w += a * w.w;
                }
                *(float4*)&ps[(ksl * 2 + rowl) * 128 + tx * 4] = acc;
            }
            __syncthreads();
            int rl = tid >> 7, c = tid & 127;
            {
                float x = ps[rl*128+c] + ps[256+rl*128+c] + ps[512+rl*128+c] + ps[768+rl*128+c]
                          + bo[l * 128 + c];
                float res = g_nodes[(r0 + rl) * 128 + c];
                const float* Wg = Wg1 + l * 384;
                float tg = x * Wg[c] + res * Wg[128 + c] + (x - res) * Wg[256 + c];
                float sg = halfsum(tg, tid, red);
                float gte = 1.f / (1.f + expf(-sg));
                float nv = x * gte + res * (1.f - gte);
                nod[rl * 128 + c] = nv;
                float mean = halfsum(nv, tid, red) * (1.f / 128.f);
                float dd = nv - mean;
                float var = halfsum(dd * dd, tid, red) * (1.f / 128.f);
                xn2[rl * 128 + c] = dd * rsqrtf(var + 1e-5f) * ln2g[l*128+c] + ln2b[l*128+c];
            }
            __syncthreads();
            {   // FF1 + GELU
                int cgr = ty >> 1;
                int cc = cgr * 128 + tx * 4;
                float4 acc = make_float4(0.f, 0.f, 0.f, 0.f);
#pragma unroll 4
                for (int k = 0; k < 128; k++) {
                    float a = xn2[rowl * 128 + k];
                    float4 w = *(const float4*)&W1_l[k * 512 + cc];
                    acc.x += a * w.x; acc.y += a * w.y; acc.z += a * w.z; acc.w += a * w.w;
                }
                float4 bb = *(const float4*)&b1[l * 512 + cc];
                float z0 = acc.x + bb.x, z1 = acc.y + bb.y, z2 = acc.z + bb.z, z3 = acc.w + bb.w;
                float4 gz;
                gz.x = 0.5f * z0 * (1.f + erff(z0 * 0.70710678118654752f));
                gz.y = 0.5f * z1 * (1.f + erff(z1 * 0.70710678118654752f));
                gz.z = 0.5f * z2 * (1.f + erff(z2 * 0.70710678118654752f));
                gz.w = 0.5f * z3 * (1.f + erff(z3 * 0.70710678118654752f));
                *(float4*)&ffs[rowl * 512 + cc] = gz;
            }
            __syncthreads();
            {   // FF2, K split 4 ways
                float4 acc = make_float4(0.f, 0.f, 0.f, 0.f);
                int kb = ksl * 128;
#pragma unroll 4
                for (int k = 0; k < 128; k++) {
                    float a = ffs[rowl * 512 + kb + k];
                    float4 w = *(const float4*)&W2_l[(kb + k) * 128 + tx * 4];
                    acc.x += a * w.x; acc.y += a * w.y; acc.z += a * w.z; acc.w += a * w.w;
                }
                *(float4*)&ps[(ksl * 2 + rowl) * 128 + tx * 4] = acc;
            }
            __syncthreads();
            {
                float x = ps[rl*128+c] + ps[256+rl*128+c] + ps[512+rl*128+c] + ps[768+rl*128+c]
                          + b2[l * 128 + c];
                float res = nod[rl * 128 + c];
                const float* Wg = Wg2 + l * 384;
                float tg = x * Wg[c] + res * Wg[128 + c] + (x - res) * Wg[256 + c];
                float sg = halfsum(tg, tid, red);
                float gte = 1.f / (1.f + expf(-sg));
                float nn = x * gte + res * (1.f - gte);
                g_nodes[(r0 + rl) * 128 + c] = nn;
                if (l < 5) {
                    float mean = halfsum(nn, tid, red) * (1.f / 128.f);
                    float dd = nn - mean;
                    float var = halfsum(dd * dd, tid, red) * (1.f / 128.f);
                    g_xn[(r0 + rl) * 128 + c] =
                        dd * rsqrtf(var + 1e-5f) * ln1g[(l+1)*128+c] + ln1b[(l+1)*128+c];
                } else {
                    float pp = nn * Wlin[c];
                    float s = warpsum(pp);
                    if (lane == 0) red[warp] = s;
                    __syncthreads();
                    if (tid == 0) {
                        float t8 = 0.f;
                        for (int q = 0; q < 8; q++) t8 += red[q];
                        g_part[bid] = t8;
                    }
                }
            }
        }
        gbar(bid);
    }

    // ================= FINAL ==============================================
    if (bid == 0) {
        float s = (tid < 128) ? g_part[tid] : 0.f;
        s = warpsum(s);
        if (lane == 0) sm[warp] = s;
        __syncthreads();
        if (tid == 0) {
            float t8 = 0.f;
            for (int q = 0; q < 8; q++) t8 += sm[q];
            out[0] = t8 + 256.f * blin[0];
        }
    }
}

extern "C" void kernel_launch(void* const* d_in, const int* in_sizes, int n_in,
                              void* d_out, int out_size) {
    fused_kernel<<<G, T>>>(
        (const int*)d_in[0],  (const float*)d_in[1],  (const int*)d_in[2],
        (const float*)d_in[3], (const float*)d_in[4],
        (const float*)d_in[5], (const float*)d_in[6],
        (const float*)d_in[7], (const float*)d_in[8],
        (const float*)d_in[9], (const float*)d_in[10],
        (const float*)d_in[11], (const float*)d_in[12],
        (const float*)d_in[13], (const float*)d_in[14],
        (const float*)d_in[15],
        (const float*)d_in[16], (const float*)d_in[17],
        (const float*)d_in[18], (const float*)d_in[19],
        (const float*)d_in[20], (const float*)d_in[21],
        (const float*)d_in[22],
        (const float*)d_in[23], (const float*)d_in[24],
        (float*)d_out);
}

// round 4
// speedup vs baseline: 2.2323x; 1.3702x over previous
#include <cuda_runtime.h>
#include <math.h>

#define G      256
#define T      256

// ---------------- device scratch ------------------------------------------
__device__ float g_nodes[256 * 128];
__device__ float g_xn   [256 * 128];
__device__ float g_q    [256 * 512];
__device__ float g_kT   [2 * 512 * 128];   // [b][c][j]
__device__ float g_v    [256 * 512];       // row-major
__device__ float g_att  [256 * 512];
__device__ float g_edges[2 * 128 * 128 * 3];
__device__ float g_part [G];

__device__ unsigned int          g_cnt[8];
__device__ unsigned int          g_root;
__device__ volatile unsigned int g_epoch;

__device__ __forceinline__ float warpsum(float v) {
#pragma unroll
    for (int s = 16; s > 0; s >>= 1) v += __shfl_xor_sync(0xffffffffu, v, s);
    return v;
}
__device__ __forceinline__ float warpmax(float v) {
#pragma unroll
    for (int s = 16; s > 0; s >>= 1) v = fmaxf(v, __shfl_xor_sync(0xffffffffu, v, s));
    return v;
}

// two-level grid barrier (256 blocks = 8 groups x 32)
__device__ __forceinline__ void gbar(int bid) {
    __syncthreads();
    if (threadIdx.x == 0) {
        __threadfence();
        unsigned int e = g_epoch;
        unsigned int t = atomicAdd(&g_cnt[bid & 7], 1u);
        if (t == 31u) {
            g_cnt[bid & 7] = 0u;
            unsigned int r = atomicAdd(&g_root, 1u);
            if (r == 7u) {
                g_root = 0u;
                __threadfence();
                g_epoch = e + 1u;
            } else {
                while (g_epoch == e) { __nanosleep(32); }
            }
        } else {
            while (g_epoch == e) { __nanosleep(32); }
        }
        __threadfence();
    }
    __syncthreads();
}

// sum over values held by threads 0..127 (others must pass 0); all 256 call
__device__ __forceinline__ float sum128(float v, int tid, float* red) {
    v = warpsum(v);
    int w = tid >> 5;
    if ((tid & 31) == 0 && w < 4) red[w] = v;
    __syncthreads();
    float s = red[0] + red[1] + red[2] + red[3];
    __syncthreads();
    return s;
}

__global__ void __launch_bounds__(T, 2)
fused_kernel(const int* __restrict__ indices, const float* __restrict__ coords,
             const int* __restrict__ bonds,   const float* __restrict__ noise,
             const float* __restrict__ atom_emb,
             const float* __restrict__ ln1g, const float* __restrict__ ln1b,
             const float* __restrict__ Wq,   const float* __restrict__ bq,
             const float* __restrict__ Wkv,  const float* __restrict__ bkv,
             const float* __restrict__ We,   const float* __restrict__ be,
             const float* __restrict__ Wo,   const float* __restrict__ bo,
             const float* __restrict__ Wg1,
             const float* __restrict__ ln2g, const float* __restrict__ ln2b,
             const float* __restrict__ W1,   const float* __restrict__ b1,
             const float* __restrict__ W2,   const float* __restrict__ b2,
             const float* __restrict__ Wg2,
             const float* __restrict__ Wlin, const float* __restrict__ blin,
             float* __restrict__ out) {
    __shared__ float sm[9920];   // 38.75 KB
    int bid = blockIdx.x, tid = threadIdx.x;
    int lane = tid & 31, warp = tid >> 5;

    // ================= SETUP ==============================================
    {
        int ez = bid * 384;
        g_edges[ez + tid] = 0.f;
        if (tid < 128) g_edges[ez + 256 + tid] = 0.f;

        int row = bid, c = tid & 127;
        float val = 0.f;
        if (tid < 128) val = (c < 127) ? atom_emb[indices[row] * 127 + c] : noise[0];
        float mean = sum128(val, tid, sm) * (1.f / 128.f);
        float d = (tid < 128) ? (val - mean) : 0.f;
        float var = sum128(d * d, tid, sm) * (1.f / 128.f);
        if (tid < 128) {
            g_nodes[row * 128 + c] = val;
            g_xn[row * 128 + c] = d * rsqrtf(var + 1e-5f) * ln1g[c] + ln1b[c];
        }
    }
    gbar(bid);

    // ================= LAYER LOOP =========================================
    for (int l = 0; l < 6; l++) {
        // ---------- QKV GEMM: 192 tiles = 16 row-tiles(16) x 12 col-tiles --
        if (bid < 192) {
            const float* Wq_l  = Wq  + l * 128 * 512;
            const float* Wkv_l = Wkv + l * 128 * 1024;
            int rt = bid / 12, ct = bid % 12;
            int r0 = rt * 16;
            float* xs = sm;                             // 16x128
            {
                const float4* src = (const float4*)(g_xn + r0 * 128);
                float4* dst = (float4*)xs;
                dst[tid] = src[tid];
                dst[tid + 256] = src[tid + 256];
            }
            __syncthreads();
            int tx = tid & 31, ty = tid >> 5;
            int cglob = ct * 128 + tx * 4;
            const float* W; int ld, cs;
            float4 bias;
            if (cglob < 512) {
                W = Wq_l; ld = 512; cs = cglob;
                bias = *(const float4*)&bq[l * 512 + cglob];
            } else {
                W = Wkv_l; ld = 1024; cs = cglob - 512;
                int cc = (cglob < 1024) ? (cglob - 512) : (cglob - 1024);
                float4 bb  = *(const float4*)&bkv[l * 1024 + cs];
                float4 bee = *(const float4*)&be[l * 512 + cc];
                bias.x = bb.x + bee.x; bias.y = bb.y + bee.y;
                bias.z = bb.z + bee.z; bias.w = bb.w + bee.w;
            }
            float acc[2][4];
#pragma unroll
            for (int r = 0; r < 2; r++) { acc[r][0]=0.f; acc[r][1]=0.f; acc[r][2]=0.f; acc[r][3]=0.f; }
#pragma unroll 8
            for (int k = 0; k < 128; k++) {
                float4 w4 = *(const float4*)&W[k * ld + cs];
#pragma unroll
                for (int r = 0; r < 2; r++) {
                    float x = xs[(ty * 2 + r) * 128 + k];
                    acc[r][0] += x * w4.x; acc[r][1] += x * w4.y;
                    acc[r][2] += x * w4.z; acc[r][3] += x * w4.w;
                }
            }
#pragma unroll
            for (int r = 0; r < 2; r++) {
                int row = r0 + ty * 2 + r;
                float4 o;
                o.x = acc[r][0] + bias.x; o.y = acc[r][1] + bias.y;
                o.z = acc[r][2] + bias.z; o.w = acc[r][3] + bias.w;
                if (cglob < 512) {
                    *(float4*)&g_q[row * 512 + cglob] = o;
                } else if (cglob < 1024) {
                    int b = row >> 7, j = row & 127, kc = cglob - 512;
                    g_kT[(b * 512 + kc    ) * 128 + j] = o.x;
                    g_kT[(b * 512 + kc + 1) * 128 + j] = o.y;
                    g_kT[(b * 512 + kc + 2) * 128 + j] = o.z;
                    g_kT[(b * 512 + kc + 3) * 128 + j] = o.w;
                } else {
                    *(float4*)&g_v[row * 512 + (cglob - 1024)] = o;
                }
            }
        } else if (bid == 192 && l == 0) {
            // ---------- edge scatter (concurrent with QKV L0) -------------
            int* bnd = (int*)sm;
            int* win = (int*)(sm + 512);
            for (int t = tid; t < 320; t += 256) bnd[t] = bonds[t];
            __syncthreads();
            if (tid < 160) {
                int i = bnd[tid * 2], j = bnd[tid * 2 + 1], w = 1;
                for (int e = tid + 1; e < 160; e++)
                    if (bnd[e * 2] == i && bnd[e * 2 + 1] == j) { w = 0; break; }
                win[tid] = w;
            }
            __syncthreads();
            if (tid < 160 && win[tid]) {
                int i = bnd[tid * 2], j = bnd[tid * 2 + 1];
                for (int b = 0; b < 2; b++) {
                    const float* cb = coords + b * 384;
                    float dx = cb[i*3]-cb[j*3], dy = cb[i*3+1]-cb[j*3+1], dz = cb[i*3+2]-cb[j*3+2];
                    float* p = &g_edges[((b * 128 + i) * 128 + j) * 3];
                    p[0] = dx; p[1] = dy; p[2] = dz;
                }
            }
            __syncthreads();
            if (tid < 160 && win[tid]) {
                int i = bnd[tid * 2], j = bnd[tid * 2 + 1];
                for (int b = 0; b < 2; b++) {
                    const float* cb = coords + b * 384;
                    float dx = cb[i*3]-cb[j*3], dy = cb[i*3+1]-cb[j*3+1], dz = cb[i*3+2]-cb[j*3+2];
                    float* p = &g_edges[((b * 128 + j) * 128 + i) * 3];
                    p[0] = -dx; p[1] = -dy; p[2] = -dz;
                }
            }
        }
        gbar(bid);

        // ---------- ATTENTION: 256 jobs = b(2) x h(8) x itile(16 of 8 rows)
        {
            const float* We_l = We + l * 3 * 512;
            int b = bid >> 7, h = (bid >> 4) & 7, it = bid & 15;
            float* tile = sm;           // 8192 f
            float* qs   = sm + 8192;    // 512 f
            float* aps  = sm + 8704;    // 1024 f
            float* wsh  = sm + 9728;    // 192 f
            {
                const float4* ks = (const float4*)(g_kT + (b * 512 + h * 64) * 128);
                float4* td = (float4*)tile;
#pragma unroll
                for (int t = 0; t < 8; t++) td[tid + t * 256] = ks[tid + t * 256];
            }
            if (tid < 128) {
                const float* qb = g_q + (b * 128 + it * 8) * 512 + h * 64;
                int i8 = tid >> 4, dq = (tid & 15) * 4;
                *(float4*)&qs[i8 * 64 + dq] = *(const float4*)&qb[i8 * 512 + dq];
            }
            if (tid < 192) {
                int c = tid / 64, d = tid % 64;
                wsh[tid] = We_l[c * 512 + h * 64 + d];
            }
            __syncthreads();

            float ec0, ec1, ec2;
            int i = it * 8 + warp;
            {
                float q0 = qs[warp * 64 + lane], q1 = qs[warp * 64 + 32 + lane];
                float qe0 = warpsum(q0 * wsh[lane]       + q1 * wsh[32 + lane]);
                float qe1 = warpsum(q0 * wsh[64 + lane]  + q1 * wsh[96 + lane]);
                float qe2 = warpsum(q0 * wsh[128 + lane] + q1 * wsh[160 + lane]);

                float ax = 0.f, ay = 0.f, az = 0.f, aw = 0.f;
#pragma unroll 16
                for (int d = 0; d < 64; d++) {
                    float qv = qs[warp * 64 + d];
                    float4 kt = *(float4*)&tile[d * 128 + lane * 4];
                    ax += qv * kt.x; ay += qv * kt.y; az += qv * kt.z; aw += qv * kt.w;
                }
                const float* eb = g_edges + (b * 128 + i) * 384 + lane * 12;
                float4 ea  = *(const float4*)(eb);
                float4 eb4 = *(const float4*)(eb + 4);
                float4 ec4 = *(const float4*)(eb + 8);
                float E0x=ea.x,  E0y=ea.y,  E0z=ea.z;
                float E1x=ea.w,  E1y=eb4.x, E1z=eb4.y;
                float E2x=eb4.z, E2y=eb4.w, E2z=ec4.x;
                float E3x=ec4.y, E3y=ec4.z, E3z=ec4.w;
                float s0 = (ax + qe0*E0x + qe1*E0y + qe2*E0z) * 0.125f;
                float s1 = (ay + qe0*E1x + qe1*E1y + qe2*E1z) * 0.125f;
                float s2 = (az + qe0*E2x + qe1*E2y + qe2*E2z) * 0.125f;
                float s3 = (aw + qe0*E3x + qe1*E3y + qe2*E3z) * 0.125f;
                float mx = warpmax(fmaxf(fmaxf(s0, s1), fmaxf(s2, s3)));
                float p0 = expf(s0 - mx), p1 = expf(s1 - mx), p2 = expf(s2 - mx), p3 = expf(s3 - mx);
                float sum = warpsum(p0 + p1 + p2 + p3);
                float inv = 1.f / sum;
                p0 *= inv; p1 *= inv; p2 *= inv; p3 *= inv;
                *(float4*)&aps[warp * 128 + lane * 4] = make_float4(p0, p1, p2, p3);
                ec0 = warpsum(p0*E0x + p1*E1x + p2*E2x + p3*E3x);
                ec1 = warpsum(p0*E0y + p1*E1y + p2*E2y + p3*E3y);
                ec2 = warpsum(p0*E0z + p1*E1z + p2*E2z + p3*E3z);
            }
            __syncthreads();
            {   // v tile [j][64]
                const float* vb = g_v + (b * 128) * 512 + h * 64;
#pragma unroll
                for (int t = 0; t < 8; t++) {
                    int idx = tid + t * 256;
                    int j = idx >> 4, dq = (idx & 15) * 4;
                    *(float4*)&tile[j * 64 + dq] = *(const float4*)&vb[j * 512 + dq];
                }
            }
            __syncthreads();
            {
                int d0 = lane * 2;
                float ox = 0.f, oy = 0.f;
#pragma unroll 8
                for (int jc = 0; jc < 32; jc++) {
                    float4 a4 = *(float4*)&aps[warp * 128 + jc * 4];
                    float2 v0 = *(float2*)&tile[(jc * 4 + 0) * 64 + d0];
                    float2 v1 = *(float2*)&tile[(jc * 4 + 1) * 64 + d0];
                    float2 v2 = *(float2*)&tile[(jc * 4 + 2) * 64 + d0];
                    float2 v3 = *(float2*)&tile[(jc * 4 + 3) * 64 + d0];
                    ox += a4.x * v0.x + a4.y * v1.x + a4.z * v2.x + a4.w * v3.x;
                    oy += a4.x * v0.y + a4.y * v1.y + a4.z * v2.y + a4.w * v3.y;
                }
                ox += ec0*wsh[d0]   + ec1*wsh[64+d0]   + ec2*wsh[128+d0];
                oy += ec0*wsh[d0+1] + ec1*wsh[64+d0+1] + ec2*wsh[128+d0+1];
                *(float2*)&g_att[(b * 128 + i) * 512 + h * 64 + d0] = make_float2(ox, oy);
            }
        }
        gbar(bid);

        // ---------- POST: 1 row per block ---------------------------------
        {
            const float* Wo_l = Wo + l * 512 * 128;
            const float* W1_l = W1 + l * 128 * 512;
            const float* W2_l = W2 + l * 512 * 128;
            float* xs  = sm;            // 512
            float* ps  = sm + 512;      // 1024
            float* xn2 = sm + 1536;     // 128
            float* nod = sm + 1664;     // 128
            float* ffs = sm + 1792;     // 512
            float* red = sm + 2304;     // 16
            int row = bid;
            ((float2*)xs)[tid] = ((const float2*)(g_att + row * 512))[tid];
            __syncthreads();
            int tx = tid & 31, ks = tid >> 5;       // 8-way K split
            {   // Wo proj
                float4 acc = make_float4(0.f, 0.f, 0.f, 0.f);
                int kb = ks * 64;
#pragma unroll 8
                for (int k = 0; k < 64; k++) {
                    float a = xs[kb + k];
                    float4 w = *(const float4*)&Wo_l[(kb + k) * 128 + tx * 4];
                    acc.x += a * w.x; acc.y += a * w.y; acc.z += a * w.z; acc.w += a * w.w;
                }
                *(float4*)&ps[ks * 128 + tx * 4] = acc;
            }
            __syncthreads();
            int c = tid & 127;
            {
                float x = 0.f, res = 0.f, tg = 0.f;
                if (tid < 128) {
                    x = ps[c] + ps[128+c] + ps[256+c] + ps[384+c]
                      + ps[512+c] + ps[640+c] + ps[768+c] + ps[896+c] + bo[l * 128 + c];
                    res = g_nodes[row * 128 + c];
                    const float* Wg = Wg1 + l * 384;
                    tg = x * Wg[c] + res * Wg[128 + c] + (x - res) * Wg[256 + c];
                }
                float sg = sum128(tg, tid, red);
                float gte = 1.f / (1.f + expf(-sg));
                float nv = (tid < 128) ? (x * gte + res * (1.f - gte)) : 0.f;
                float mean = sum128(nv, tid, red) * (1.f / 128.f);
                float dd = (tid < 128) ? (nv - mean) : 0.f;
                float var = sum128(dd * dd, tid, red) * (1.f / 128.f);
                if (tid < 128) {
                    nod[c] = nv;
                    xn2[c] = dd * rsqrtf(var + 1e-5f) * ln2g[l*128+c] + ln2b[l*128+c];
                }
            }
            __syncthreads();
            {   // FF1 partials (2-way K split x 128 col-quads)
                int cq = (tid & 127) * 4, ks2 = tid >> 7, kb = ks2 * 64;
                float4 acc = make_float4(0.f, 0.f, 0.f, 0.f);
#pragma unroll 8
                for (int k = 0; k < 64; k++) {
                    float a = xn2[kb + k];
                    float4 w = *(const float4*)&W1_l[(kb + k) * 512 + cq];
                    acc.x += a * w.x; acc.y += a * w.y; acc.z += a * w.z; acc.w += a * w.w;
                }
                *(float4*)&ps[ks2 * 512 + cq] = acc;
            }
            __syncthreads();
            {   // combine + GELU
#pragma unroll
                for (int q = 0; q < 2; q++) {
                    int cc = tid + q * 256;
                    float z = ps[cc] + ps[512 + cc] + b1[l * 512 + cc];
                    ffs[cc] = 0.5f * z * (1.f + erff(z * 0.70710678118654752f));
                }
            }
            __syncthreads();
            {   // FF2
                float4 acc = make_float4(0.f, 0.f, 0.f, 0.f);
                int kb = ks * 64;
#pragma unroll 8
                for (int k = 0; k < 64; k++) {
                    float a = ffs[kb + k];
                    float4 w = *(const float4*)&W2_l[(kb + k) * 128 + tx * 4];
                    acc.x += a * w.x; acc.y += a * w.y; acc.z += a * w.z; acc.w += a * w.w;
                }
                *(float4*)&ps[ks * 128 + tx * 4] = acc;
            }
            __syncthreads();
            {
                float x = 0.f, res = 0.f, tg = 0.f;
                if (tid < 128) {
                    x = ps[c] + ps[128+c] + ps[256+c] + ps[384+c]
                      + ps[512+c] + ps[640+c] + ps[768+c] + ps[896+c] + b2[l * 128 + c];
                    res = nod[c];
                    const float* Wg = Wg2 + l * 384;
                    tg = x * Wg[c] + res * Wg[128 + c] + (x - res) * Wg[256 + c];
                }
                float sg = sum128(tg, tid, red);
                float gte = 1.f / (1.f + expf(-sg));
                float nn = (tid < 128) ? (x * gte + res * (1.f - gte)) : 0.f;
                if (tid < 128) g_nodes[row * 128 + c] = nn;
                if (l < 5) {
                    float mean = sum128(nn, tid, red) * (1.f / 128.f);
                    float dd = (tid < 128) ? (nn - mean) : 0.f;
                    float var = sum128(dd * dd, tid, red) * (1.f / 128.f);
                    if (tid < 128)
                        g_xn[row * 128 + c] =
                            dd * rsqrtf(var + 1e-5f) * ln1g[(l+1)*128+c] + ln1b[(l+1)*128+c];
                } else {
                    float pp = (tid < 128) ? (nn * Wlin[c]) : 0.f;
                    float s = sum128(pp, tid, red);
                    if (tid == 0) g_part[bid] = s;
                }
            }
        }
        gbar(bid);
    }

    // ================= FINAL ==============================================
    if (bid == 0) {
        float s = g_part[tid];
        s = warpsum(s);
        if (lane == 0) sm[warp] = s;
        __syncthreads();
        if (tid == 0) {
            float t8 = 0.f;
            for (int q = 0; q < 8; q++) t8 += sm[q];
            out[0] = t8 + 256.f * blin[0];
        }
    }
}

extern "C" void kernel_launch(void* const* d_in, const int* in_sizes, int n_in,
                              void* d_out, int out_size) {
    fused_kernel<<<G, T>>>(
        (const int*)d_in[0],  (const float*)d_in[1],  (const int*)d_in[2],
        (const float*)d_in[3], (const float*)d_in[4],
        (const float*)d_in[5], (const float*)d_in[6],
        (const float*)d_in[7], (const float*)d_in[8],
        (const float*)d_in[9], (const float*)d_in[10],
        (const float*)d_in[11], (const float*)d_in[12],
        (const float*)d_in[13], (const float*)d_in[14],
        (const float*)d_in[15],
        (const float*)d_in[16], (const float*)d_in[17],
        (const float*)d_in[18], (const float*)d_in[19],
        (const float*)d_in[20], (const float*)d_in[21],
        (const float*)d_in[22],
        (const float*)d_in[23], (const float*)d_in[24],
        (float*)d_out);
}

// round 5
// speedup vs baseline: 2.4777x; 1.1099x over previous
#include <cuda_runtime.h>
#include <math.h>

#define G 296
#define T 256

// ---------------- device scratch ------------------------------------------
__device__ float g_nodes[256 * 128];
__device__ float g_xn   [256 * 128];
__device__ float g_q  [2][256 * 512];
__device__ float g_kT [2][1024 * 128];   // [p][b*512+c][j]
__device__ float g_v  [2][256 * 512];
__device__ float g_att  [256 * 512];
__device__ float g_edges[2 * 128 * 128 * 3];
__device__ float g_part [256];

// dataflow flags (monotonic within a launch; reset by the final block)
__device__ volatile int f_rt[8];     // xn row-groups of 32 rows: target 32*(l+1)
__device__ volatile int f_qkv[48];   // per (b, ct64): target 4*(l+1)
__device__ volatile int f_att[32];   // per (b, it8):  target 8*(l+1)
__device__ volatile int f_ez;        // edge zeroing arrivals (296)
__device__ volatile int f_edge;      // edge scatter done (1)
__device__ int          f_done;      // POST l5 arrivals (256)

__device__ __forceinline__ float warpsum(float v) {
#pragma unroll
    for (int s = 16; s > 0; s >>= 1) v += __shfl_xor_sync(0xffffffffu, v, s);
    return v;
}
__device__ __forceinline__ float warpmax(float v) {
#pragma unroll
    for (int s = 16; s > 0; s >>= 1) v = fmaxf(v, __shfl_xor_sync(0xffffffffu, v, s));
    return v;
}

__device__ __forceinline__ void waitge(volatile int* f, int tgt) {
    if (*f < tgt) {
        int ns = 40;
        do { __nanosleep(ns); if (ns < 512) ns <<= 1; } while (*f < tgt);
    }
    __threadfence();   // acquire
}
__device__ __forceinline__ void sig(volatile int* f) {
    __threadfence();   // release (caller: after __syncthreads)
    atomicAdd((int*)f, 1);
}

// sum over values held by threads 0..127 (others pass 0); all 256 call
__device__ __forceinline__ float sum128(float v, int tid, float* red) {
    v = warpsum(v);
    int w = tid >> 5;
    if ((tid & 31) == 0 && w < 4) red[w] = v;
    __syncthreads();
    float s = red[0] + red[1] + red[2] + red[3];
    __syncthreads();
    return s;
}

__global__ void __launch_bounds__(T, 2)
fused_kernel(const int* __restrict__ indices, const float* __restrict__ coords,
             const int* __restrict__ bonds,   const float* __restrict__ noise,
             const float* __restrict__ atom_emb,
             const float* __restrict__ ln1g, const float* __restrict__ ln1b,
             const float* __restrict__ Wq,   const float* __restrict__ bq,
             const float* __restrict__ Wkv,  const float* __restrict__ bkv,
             const float* __restrict__ We,   const float* __restrict__ be,
             const float* __restrict__ Wo,   const float* __restrict__ bo,
             const float* __restrict__ Wg1,
             const float* __restrict__ ln2g, const float* __restrict__ ln2b,
             const float* __restrict__ W1,   const float* __restrict__ b1,
             const float* __restrict__ W2,   const float* __restrict__ b2,
             const float* __restrict__ Wg2,
             const float* __restrict__ Wlin, const float* __restrict__ blin,
             float* __restrict__ out) {
    __shared__ float sm[9920];   // 38.75 KB
    int bid = blockIdx.x, tid = threadIdx.x;
    int lane = tid & 31, warp = tid >> 5;

    // ---- zero edges (all blocks) ----------------------------------------
    {
        int z0 = bid * 336;
#pragma unroll
        for (int q = 0; q < 2; q++) {
            int idx = z0 + tid + q * 256;
            if (tid + q * 256 < 336 && idx < 98304) g_edges[idx] = 0.f;
        }
    }
    __syncthreads();
    if (tid == 0) sig(&f_ez);

    // ---- setup: node embed + LN1 (blocks 0..255, one row each) ----------
    if (bid < 256) {
        int row = bid, c = tid & 127;
        float val = 0.f;
        if (tid < 128) val = (c < 127) ? atom_emb[indices[row] * 127 + c] : noise[0];
        float mean = sum128(val, tid, sm) * (1.f / 128.f);
        float d = (tid < 128) ? (val - mean) : 0.f;
        float var = sum128(d * d, tid, sm) * (1.f / 128.f);
        if (tid < 128) {
            g_nodes[row * 128 + c] = val;
            g_xn[row * 128 + c] = d * rsqrtf(var + 1e-5f) * ln1g[c] + ln1b[c];
        }
        __syncthreads();
        if (tid == 0) sig(&f_rt[row >> 5]);
    }

    // ---- edge scatter (block 295 only) ----------------------------------
    if (bid == 295) {
        if (tid == 0) waitge(&f_ez, 296);
        __syncthreads();
        int* bnd = (int*)sm;
        int* win = (int*)(sm + 512);
        for (int t = tid; t < 320; t += 256) bnd[t] = bonds[t];
        __syncthreads();
        if (tid < 160) {
            int i = bnd[tid * 2], j = bnd[tid * 2 + 1], w = 1;
            for (int e = tid + 1; e < 160; e++)
                if (bnd[e * 2] == i && bnd[e * 2 + 1] == j) { w = 0; break; }
            win[tid] = w;
        }
        __syncthreads();
        if (tid < 160 && win[tid]) {
            int i = bnd[tid * 2], j = bnd[tid * 2 + 1];
            for (int b = 0; b < 2; b++) {
                const float* cb = coords + b * 384;
                float dx = cb[i*3]-cb[j*3], dy = cb[i*3+1]-cb[j*3+1], dz = cb[i*3+2]-cb[j*3+2];
                float* p = &g_edges[((b * 128 + i) * 128 + j) * 3];
                p[0] = dx; p[1] = dy; p[2] = dz;
            }
        }
        __syncthreads();
        if (tid < 160 && win[tid]) {
            int i = bnd[tid * 2], j = bnd[tid * 2 + 1];
            for (int b = 0; b < 2; b++) {
                const float* cb = coords + b * 384;
                float dx = cb[i*3]-cb[j*3], dy = cb[i*3+1]-cb[j*3+1], dz = cb[i*3+2]-cb[j*3+2];
                float* p = &g_edges[((b * 128 + j) * 128 + i) * 3];
                p[0] = -dx; p[1] = -dy; p[2] = -dz;
            }
        }
        __syncthreads();
        if (tid == 0) sig(&f_edge);
    }

    // ================= LAYER LOOP =========================================
    for (int l = 0; l < 6; l++) {
        int p = l & 1;

        // ---------- QKV GEMM: 192 tiles (8 rt of 32 rows x 24 ct of 64) --
        if (bid >= 103 && bid < 295) {
            int t = 294 - bid;
            int rt = t / 24, ct = t % 24;
            int r0 = rt * 32, b = rt >> 2;
            int cbase = ct * 64;
            if (tid == 0) waitge(&f_rt[rt], 32 * (l + 1));
            __syncthreads();

            float* xs = sm;   // 32x128
            {
                const float4* src = (const float4*)(g_xn + r0 * 128);
                float4* dst = (float4*)xs;
#pragma unroll
                for (int q = 0; q < 4; q++) dst[tid + q * 256] = src[tid + q * 256];
            }
            __syncthreads();

            int tx = tid & 15, ty = tid >> 4;
            int c4 = cbase + tx * 4;
            const float* W; int ld, cs;
            float4 bias;
            if (cbase < 512) {
                W = Wq + l * 128 * 512; ld = 512; cs = c4;
                bias = *(const float4*)&bq[l * 512 + c4];
            } else {
                W = Wkv + l * 128 * 1024; ld = 1024; cs = c4 - 512;
                int cc = (cbase < 1024) ? (c4 - 512) : (c4 - 1024);
                float4 bb  = *(const float4*)&bkv[l * 1024 + cs];
                float4 bee = *(const float4*)&be[l * 512 + cc];
                bias.x = bb.x + bee.x; bias.y = bb.y + bee.y;
                bias.z = bb.z + bee.z; bias.w = bb.w + bee.w;
            }
            float acc[2][4];
#pragma unroll
            for (int r = 0; r < 2; r++) { acc[r][0]=0.f; acc[r][1]=0.f; acc[r][2]=0.f; acc[r][3]=0.f; }
#pragma unroll 8
            for (int k = 0; k < 128; k++) {
                float4 w4 = *(const float4*)&W[k * ld + cs];
#pragma unroll
                for (int r = 0; r < 2; r++) {
                    float x = xs[(ty * 2 + r) * 128 + k];
                    acc[r][0] += x * w4.x; acc[r][1] += x * w4.y;
                    acc[r][2] += x * w4.z; acc[r][3] += x * w4.w;
                }
            }
#pragma unroll
            for (int r = 0; r < 2; r++) {
                int row = r0 + ty * 2 + r;
                float4 o;
                o.x = acc[r][0] + bias.x; o.y = acc[r][1] + bias.y;
                o.z = acc[r][2] + bias.z; o.w = acc[r][3] + bias.w;
                if (cbase < 512) {
                    *(float4*)&g_q[p][row * 512 + c4] = o;
                } else if (cbase < 1024) {
                    int j = row & 127, kc = c4 - 512;
                    g_kT[p][(b * 512 + kc    ) * 128 + j] = o.x;
                    g_kT[p][(b * 512 + kc + 1) * 128 + j] = o.y;
                    g_kT[p][(b * 512 + kc + 2) * 128 + j] = o.z;
                    g_kT[p][(b * 512 + kc + 3) * 128 + j] = o.w;
                } else {
                    *(float4*)&g_v[p][row * 512 + (c4 - 1024)] = o;
                }
            }
            __syncthreads();
            if (tid == 0) sig(&f_qkv[b * 24 + ct]);
        }

        // ---------- ATTENTION: 256 jobs (b x h x it8) ---------------------
        if (bid < 256) {
            const float* We_l = We + l * 3 * 512;
            int b = bid >> 7, h = (bid >> 4) & 7, it = bid & 15;
            if      (tid == 0)  waitge(&f_qkv[b * 24 + h],      4 * (l + 1));
            else if (tid == 32) waitge(&f_qkv[b * 24 + 8 + h],  4 * (l + 1));
            else if (tid == 64) waitge(&f_qkv[b * 24 + 16 + h], 4 * (l + 1));
            else if (tid == 96) waitge(&f_edge, 1);
            __syncthreads();

            float* tile = sm;           // 8192 f
            float* qs   = sm + 8192;    // 512 f
            float* aps  = sm + 8704;    // 1024 f
            float* wsh  = sm + 9728;    // 192 f
            int i = it * 8 + warp;

            // prefetch edges for this warp's row
            const float* ebp = g_edges + (b * 128 + i) * 384 + lane * 12;
            float4 ea  = *(const float4*)(ebp);
            float4 eb4 = *(const float4*)(ebp + 4);
            float4 ec4 = *(const float4*)(ebp + 8);

            {
                const float4* ks = (const float4*)(g_kT[p] + (b * 512 + h * 64) * 128);
                float4* td = (float4*)tile;
#pragma unroll
                for (int t = 0; t < 8; t++) td[tid + t * 256] = ks[tid + t * 256];
            }
            if (tid < 128) {
                const float* qb = g_q[p] + (b * 128 + it * 8) * 512 + h * 64;
                int i8 = tid >> 4, dq = (tid & 15) * 4;
                *(float4*)&qs[i8 * 64 + dq] = *(const float4*)&qb[i8 * 512 + dq];
            }
            if (tid < 192) {
                int c = tid / 64, d = tid % 64;
                wsh[tid] = We_l[c * 512 + h * 64 + d];
            }
            __syncthreads();

            float ec0, ec1, ec2;
            {
                float q0 = qs[warp * 64 + lane], q1 = qs[warp * 64 + 32 + lane];
                float qe0 = warpsum(q0 * wsh[lane]       + q1 * wsh[32 + lane]);
                float qe1 = warpsum(q0 * wsh[64 + lane]  + q1 * wsh[96 + lane]);
                float qe2 = warpsum(q0 * wsh[128 + lane] + q1 * wsh[160 + lane]);

                float ax = 0.f, ay = 0.f, az = 0.f, aw = 0.f;
#pragma unroll 16
                for (int d = 0; d < 64; d++) {
                    float qv = qs[warp * 64 + d];
                    float4 kt = *(float4*)&tile[d * 128 + lane * 4];
                    ax += qv * kt.x; ay += qv * kt.y; az += qv * kt.z; aw += qv * kt.w;
                }
                float E0x=ea.x,  E0y=ea.y,  E0z=ea.z;
                float E1x=ea.w,  E1y=eb4.x, E1z=eb4.y;
                float E2x=eb4.z, E2y=eb4.w, E2z=ec4.x;
                float E3x=ec4.y, E3y=ec4.z, E3z=ec4.w;
                float s0 = (ax + qe0*E0x + qe1*E0y + qe2*E0z) * 0.125f;
                float s1 = (ay + qe0*E1x + qe1*E1y + qe2*E1z) * 0.125f;
                float s2 = (az + qe0*E2x + qe1*E2y + qe2*E2z) * 0.125f;
                float s3 = (aw + qe0*E3x + qe1*E3y + qe2*E3z) * 0.125f;
                float mx = warpmax(fmaxf(fmaxf(s0, s1), fmaxf(s2, s3)));
                float p0 = expf(s0 - mx), p1 = expf(s1 - mx), p2 = expf(s2 - mx), p3 = expf(s3 - mx);
                float sum = warpsum(p0 + p1 + p2 + p3);
                float inv = 1.f / sum;
                p0 *= inv; p1 *= inv; p2 *= inv; p3 *= inv;
                *(float4*)&aps[warp * 128 + lane * 4] = make_float4(p0, p1, p2, p3);
                ec0 = warpsum(p0*E0x + p1*E1x + p2*E2x + p3*E3x);
                ec1 = warpsum(p0*E0y + p1*E1y + p2*E2y + p3*E3y);
                ec2 = warpsum(p0*E0z + p1*E1z + p2*E2z + p3*E3z);
            }
            __syncthreads();
            {   // v tile [j][64]
                const float* vb = g_v[p] + (b * 128) * 512 + h * 64;
#pragma unroll
                for (int t = 0; t < 8; t++) {
                    int idx = tid + t * 256;
                    int j = idx >> 4, dq = (idx & 15) * 4;
                    *(float4*)&tile[j * 64 + dq] = *(const float4*)&vb[j * 512 + dq];
                }
            }
            __syncthreads();
            {
                int d0 = lane * 2;
                float ox = 0.f, oy = 0.f;
#pragma unroll 8
                for (int jc = 0; jc < 32; jc++) {
                    float4 a4 = *(float4*)&aps[warp * 128 + jc * 4];
                    float2 v0 = *(float2*)&tile[(jc * 4 + 0) * 64 + d0];
                    float2 v1 = *(float2*)&tile[(jc * 4 + 1) * 64 + d0];
                    float2 v2 = *(float2*)&tile[(jc * 4 + 2) * 64 + d0];
                    float2 v3 = *(float2*)&tile[(jc * 4 + 3) * 64 + d0];
                    ox += a4.x * v0.x + a4.y * v1.x + a4.z * v2.x + a4.w * v3.x;
                    oy += a4.x * v0.y + a4.y * v1.y + a4.z * v2.y + a4.w * v3.y;
                }
                ox += ec0*wsh[d0]   + ec1*wsh[64+d0]   + ec2*wsh[128+d0];
                oy += ec0*wsh[d0+1] + ec1*wsh[64+d0+1] + ec2*wsh[128+d0+1];
                *(float2*)&g_att[(b * 128 + i) * 512 + h * 64 + d0] = make_float2(ox, oy);
            }
            __syncthreads();
            if (tid == 0) sig(&f_att[b * 16 + it]);
        }

        // ---------- POST: blocks 0..255, one row each ---------------------
        if (bid < 256) {
            int row = bid;
            if (tid == 0) waitge(&f_att[row >> 3], 8 * (l + 1));
            __syncthreads();

            const float* Wo_l = Wo + l * 512 * 128;
            const float* W1_l = W1 + l * 128 * 512;
            const float* W2_l = W2 + l * 512 * 128;
            float* xs  = sm;            // 512
            float* ps  = sm + 512;      // 1024
            float* xn2 = sm + 1536;     // 128
            float* nod = sm + 1664;     // 128
            float* ffs = sm + 1792;     // 512
            float* red = sm + 2304;     // 16
            ((float2*)xs)[tid] = ((const float2*)(g_att + row * 512))[tid];
            __syncthreads();
            int tx = tid & 31, ks = tid >> 5;       // 8-way K split
            {   // Wo proj
                float4 acc = make_float4(0.f, 0.f, 0.f, 0.f);
                int kb = ks * 64;
#pragma unroll 8
                for (int k = 0; k < 64; k++) {
                    float a = xs[kb + k];
                    float4 w = *(const float4*)&Wo_l[(kb + k) * 128 + tx * 4];
                    acc.x += a * w.x; acc.y += a * w.y; acc.z += a * w.z; acc.w += a * w.w;
                }
                *(float4*)&ps[ks * 128 + tx * 4] = acc;
            }
            __syncthreads();
            int c = tid & 127;
            {
                float x = 0.f, res = 0.f, tg = 0.f;
                if (tid < 128) {
                    x = ps[c] + ps[128+c] + ps[256+c] + ps[384+c]
                      + ps[512+c] + ps[640+c] + ps[768+c] + ps[896+c] + bo[l * 128 + c];
                    res = g_nodes[row * 128 + c];
                    const float* Wg = Wg1 + l * 384;
                    tg = x * Wg[c] + res * Wg[128 + c] + (x - res) * Wg[256 + c];
                }
                float sg = sum128(tg, tid, red);
                float gte = 1.f / (1.f + expf(-sg));
                float nv = (tid < 128) ? (x * gte + res * (1.f - gte)) : 0.f;
                float mean = sum128(nv, tid, red) * (1.f / 128.f);
                float dd = (tid < 128) ? (nv - mean) : 0.f;
                float var = sum128(dd * dd, tid, red) * (1.f / 128.f);
                if (tid < 128) {
                    nod[c] = nv;
                    xn2[c] = dd * rsqrtf(var + 1e-5f) * ln2g[l*128+c] + ln2b[l*128+c];
                }
            }
            __syncthreads();
            {   // FF1 partials (2-way K split x 128 col-quads)
                int cq = (tid & 127) * 4, ks2 = tid >> 7, kb = ks2 * 64;
                float4 acc = make_float4(0.f, 0.f, 0.f, 0.f);
#pragma unroll 8
                for (int k = 0; k < 64; k++) {
                    float a = xn2[kb + k];
                    float4 w = *(const float4*)&W1_l[(kb + k) * 512 + cq];
                    acc.x += a * w.x; acc.y += a * w.y; acc.z += a * w.z; acc.w += a * w.w;
                }
                *(float4*)&ps[ks2 * 512 + cq] = acc;
            }
            __syncthreads();
            {   // combine + GELU
#pragma unroll
                for (int q = 0; q < 2; q++) {
                    int cc = tid + q * 256;
                    float z = ps[cc] + ps[512 + cc] + b1[l * 512 + cc];
                    ffs[cc] = 0.5f * z * (1.f + erff(z * 0.70710678118654752f));
                }
            }
            __syncthreads();
            {   // FF2
                float4 acc = make_float4(0.f, 0.f, 0.f, 0.f);
                int kb = ks * 64;
#pragma unroll 8
                for (int k = 0; k < 64; k++) {
                    float a = ffs[kb + k];
                    float4 w = *(const float4*)&W2_l[(kb + k) * 128 + tx * 4];
                    acc.x += a * w.x; acc.y += a * w.y; acc.z += a * w.z; acc.w += a * w.w;
                }
                *(float4*)&ps[ks * 128 + tx * 4] = acc;
            }
            __syncthreads();
            {
                float x = 0.f, res = 0.f, tg = 0.f;
                if (tid < 128) {
                    x = ps[c] + ps[128+c] + ps[256+c] + ps[384+c]
                      + ps[512+c] + ps[640+c] + ps[768+c] + ps[896+c] + b2[l * 128 + c];
                    res = nod[c];
                    const float* Wg = Wg2 + l * 384;
                    tg = x * Wg[c] + res * Wg[128 + c] + (x - res) * Wg[256 + c];
                }
                float sg = sum128(tg, tid, red);
                float gte = 1.f / (1.f + expf(-sg));
                float nn = (tid < 128) ? (x * gte + res * (1.f - gte)) : 0.f;
                if (tid < 128) g_nodes[row * 128 + c] = nn;
                if (l < 5) {
                    float mean = sum128(nn, tid, red) * (1.f / 128.f);
                    float dd = (tid < 128) ? (nn - mean) : 0.f;
                    float var = sum128(dd * dd, tid, red) * (1.f / 128.f);
                    if (tid < 128)
                        g_xn[row * 128 + c] =
                            dd * rsqrtf(var + 1e-5f) * ln1g[(l+1)*128+c] + ln1b[(l+1)*128+c];
                    __syncthreads();
                    if (tid == 0) sig(&f_rt[row >> 5]);
                } else {
                    float pp = (tid < 128) ? (nn * Wlin[c]) : 0.f;
                    float s = sum128(pp, tid, red);
                    if (tid == 0) g_part[row] = s;
                    __syncthreads();
                    // last arrival does the final reduction + flag reset
                    if (tid == 0) {
                        __threadfence();
                        int old = atomicAdd(&f_done, 1);
                        ((int*)sm)[0] = (old == 255) ? 1 : 0;
                    }
                    __syncthreads();
                    if (((int*)sm)[0]) {
                        __threadfence();
                        float v = g_part[tid];
                        v = warpsum(v);
                        if (lane == 0) sm[8 + warp] = v;
                        __syncthreads();
                        if (tid == 0) {
                            float t8 = 0.f;
                            for (int q = 0; q < 8; q++) t8 += sm[8 + q];
                            out[0] = t8 + 256.f * blin[0];
                        }
                        // reset all flags for the next launch
                        if (tid < 8)  f_rt[tid] = 0;
                        if (tid < 48) f_qkv[tid] = 0;
                        if (tid < 32) f_att[tid] = 0;
                        if (tid == 0) { f_ez = 0; f_edge = 0; f_done = 0; }
                    }
                }
            }
        }
    }
}

extern "C" void kernel_launch(void* const* d_in, const int* in_sizes, int n_in,
                              void* d_out, int out_size) {
    fused_kernel<<<G, T>>>(
        (const int*)d_in[0],  (const float*)d_in[1],  (const int*)d_in[2],
        (const float*)d_in[3], (const float*)d_in[4],
        (const float*)d_in[5], (const float*)d_in[6],
        (const float*)d_in[7], (const float*)d_in[8],
        (const float*)d_in[9], (const float*)d_in[10],
        (const float*)d_in[11], (const float*)d_in[12],
        (const float*)d_in[13], (const float*)d_in[14],
        (const float*)d_in[15],
        (const float*)d_in[16], (const float*)d_in[17],
        (const float*)d_in[18], (const float*)d_in[19],
        (const float*)d_in[20], (const float*)d_in[21],
        (const float*)d_in[22],
        (const float*)d_in[23], (const float*)d_in[24],
        (float*)d_out);
}